// round 2
// baseline (speedup 1.0000x reference)
#include <cuda_runtime.h>

#define N_NODES 50000
#define N_EDGES 200000
#define F_IN 100
#define HID 1024

// Scratch (no device allocation allowed)
__device__ float g_w[F_IN];
__device__ float g_c;
__device__ float g_deg[N_NODES];
__device__ float g_dinv[N_NODES];
__device__ float g_p[N_NODES];   // p[n] = (x[n]·w) * dinv[n]
__device__ int   g_is64;         // 1 if edge buffer is int64-layout, else 0 (int32)

// K0: detect edge index dtype layout. For int64 (little-endian) values in
// [0, 50000), every odd 32-bit word is 0. For int32 random edges, odd words
// are random node ids — P(1024 consecutive zeros) ~ 0.
__global__ void detect_dtype(const int* __restrict__ ebuf) {
    // single block, 256 threads, check words [1,3,5,...,2047]
    __shared__ int any_nonzero;
    if (threadIdx.x == 0) any_nonzero = 0;
    __syncthreads();
    for (int i = threadIdx.x; i < 1024; i += blockDim.x) {
        if (ebuf[2 * i + 1] != 0) any_nonzero = 1;
    }
    __syncthreads();
    if (threadIdx.x == 0) g_is64 = any_nonzero ? 0 : 1;
}

// K1: blocks 0..F_IN-1 compute w[b] = W1[b,:]·W_head ; block F_IN computes c
__global__ void fold_head(const float* __restrict__ W1,
                          const float* __restrict__ b1,
                          const float* __restrict__ Wh,
                          const float* __restrict__ bh) {
    __shared__ float red[256];
    int b = blockIdx.x;
    int t = threadIdx.x;
    float acc = 0.f;
    if (b < F_IN) {
        const float* row = W1 + (long long)b * HID;
        for (int k = t; k < HID; k += 256) acc += row[k] * Wh[k];
    } else {
        for (int k = t; k < HID; k += 256) acc += b1[k] * Wh[k];
    }
    red[t] = acc;
    __syncthreads();
    for (int s = 128; s > 0; s >>= 1) {
        if (t < s) red[t] += red[t + s];
        __syncthreads();
    }
    if (t == 0) {
        if (b < F_IN) g_w[b] = red[0];
        else          g_c   = red[0] + bh[0];
    }
}

// K2: reset degrees to 1.0 (self loop) — required every graph replay
__global__ void deg_init() {
    int i = blockIdx.x * blockDim.x + threadIdx.x;
    if (i < N_NODES) g_deg[i] = 1.0f;
}

__device__ __forceinline__ int load_edge(const int* ebuf, long long pos) {
    // pos in element units within the logical [2*N_EDGES] int array
    return g_is64 ? ebuf[2 * pos] : ebuf[pos];
}

// K3: accumulate in-degree over edges
__global__ void deg_accum(const int* __restrict__ ebuf) {
    int e = blockIdx.x * blockDim.x + threadIdx.x;
    if (e < N_EDGES) {
        int dst = load_edge(ebuf, (long long)N_EDGES + e);
        if (dst >= 0 && dst < N_NODES)
            atomicAdd(&g_deg[dst], 1.0f);
    }
}

// K4: warp-per-node dot product s = x[n]·w; write dinv, p, self-loop + bias
__global__ void node_kernel(const float* __restrict__ x, float* __restrict__ out) {
    __shared__ float sw[F_IN];
    int t = threadIdx.x;
    for (int i = t; i < F_IN; i += blockDim.x) sw[i] = g_w[i];
    __syncthreads();

    int gwarp = (blockIdx.x * blockDim.x + t) >> 5;
    int lane  = t & 31;
    if (gwarp >= N_NODES) return;

    const float* xr = x + (long long)gwarp * F_IN;
    float acc = xr[lane]      * sw[lane]
              + xr[lane + 32] * sw[lane + 32]
              + xr[lane + 64] * sw[lane + 64];
    if (lane < 4) acc += xr[lane + 96] * sw[lane + 96];

    #pragma unroll
    for (int o = 16; o > 0; o >>= 1)
        acc += __shfl_down_sync(0xffffffffu, acc, o);

    if (lane == 0) {
        float d = rsqrtf(g_deg[gwarp]);   // deg >= 1 always (self loop)
        g_dinv[gwarp] = d;
        g_p[gwarp]    = acc * d;
        out[gwarp]    = g_c + acc * d * d;   // self-loop message + folded bias
    }
}

// K5: scatter edge messages: out[dst] += p[src]*dinv[dst]
__global__ void edge_scatter(const int* __restrict__ ebuf,
                             float* __restrict__ out) {
    int e = blockIdx.x * blockDim.x + threadIdx.x;
    if (e < N_EDGES) {
        int s = load_edge(ebuf, e);
        int d = load_edge(ebuf, (long long)N_EDGES + e);
        if (s >= 0 && s < N_NODES && d >= 0 && d < N_NODES)
            atomicAdd(&out[d], g_p[s] * g_dinv[d]);
    }
}

extern "C" void kernel_launch(void* const* d_in, const int* in_sizes, int n_in,
                              void* d_out, int out_size) {
    const float* state = (const float*)d_in[0];  // [N, 100, 1] f32
    const int*   ebuf  = (const int*)  d_in[1];  // [2, 200000] int32 (or int64 layout)
    const float* W1    = (const float*)d_in[2];  // [100, 1024]
    const float* b1    = (const float*)d_in[3];  // [1024]
    const float* Wh    = (const float*)d_in[4];  // [1024, 1]
    const float* bh    = (const float*)d_in[5];  // [1]
    float* out = (float*)d_out;                  // [N, 1]

    detect_dtype<<<1, 256>>>(ebuf);
    fold_head   <<<F_IN + 1, 256>>>(W1, b1, Wh, bh);
    deg_init    <<<(N_NODES + 255) / 256, 256>>>();
    deg_accum   <<<(N_EDGES + 255) / 256, 256>>>(ebuf);
    node_kernel <<<(N_NODES * 32 + 255) / 256, 256>>>(state, out);
    edge_scatter<<<(N_EDGES + 255) / 256, 256>>>(ebuf, out);
}

// round 3
// speedup vs baseline: 1.3205x; 1.3205x over previous
#include <cuda_runtime.h>

#define N_NODES 50000
#define N_EDGES 200000
#define F_IN 100
#define HID 1024

#define NB_DEG   ((N_NODES + 255) / 256)          // 196 blocks for per-node work
#define NB_NODE  ((N_NODES * 32 + 255) / 256)     // 6250 blocks, warp-per-node
#define NB_EDGE  ((N_EDGES + 255) / 256)          // 782 blocks, thread-per-edge

// Scratch (no device allocation allowed)
__device__ float g_w[F_IN];
__device__ float g_c;
__device__ float g_deg[N_NODES];
__device__ float g_dinv[N_NODES];
__device__ float g_s[N_NODES];   // s[n] = x[n]·w
__device__ float g_p[N_NODES];   // p[n] = s[n] * dinv[n]
__device__ int   g_is64;

// ---------------------------------------------------------------------------
// K1 (fused setup): block 0 = dtype detect, blocks 1..101 = head fold,
// blocks 102.. = degree init to 1.0 (self loop). All independent.
// ---------------------------------------------------------------------------
__global__ void setup_kernel(const int* __restrict__ ebuf,
                             const float* __restrict__ W1,
                             const float* __restrict__ b1,
                             const float* __restrict__ Wh,
                             const float* __restrict__ bh) {
    int blk = blockIdx.x;
    int t = threadIdx.x;

    if (blk == 0) {
        // int64-little-endian edge values < 50000 => every odd 32-bit word is 0.
        __shared__ int any_nonzero;
        if (t == 0) any_nonzero = 0;
        __syncthreads();
        for (int i = t; i < 1024; i += blockDim.x)
            if (ebuf[2 * i + 1] != 0) any_nonzero = 1;
        __syncthreads();
        if (t == 0) g_is64 = any_nonzero ? 0 : 1;
        return;
    }
    if (blk <= F_IN + 1) {
        int b = blk - 1;  // 0..100
        __shared__ float red[256];
        float acc = 0.f;
        if (b < F_IN) {
            const float* row = W1 + (long long)b * HID;
            for (int k = t; k < HID; k += 256) acc += row[k] * Wh[k];
        } else {
            for (int k = t; k < HID; k += 256) acc += b1[k] * Wh[k];
        }
        red[t] = acc;
        __syncthreads();
        for (int s = 128; s > 0; s >>= 1) {
            if (t < s) red[t] += red[t + s];
            __syncthreads();
        }
        if (t == 0) {
            if (b < F_IN) g_w[b] = red[0];
            else          g_c   = red[0] + bh[0];
        }
        return;
    }
    // degree init
    int i = (blk - (F_IN + 2)) * 256 + t;
    if (i < N_NODES) g_deg[i] = 1.0f;
}

__device__ __forceinline__ int load_edge(const int* ebuf, long long pos) {
    if (g_is64) return ((const int2*)ebuf)[pos].x;   // coalesced 8B load, take lo word
    return ebuf[pos];
}

// ---------------------------------------------------------------------------
// K2 (fused): blocks [0, NB_NODE) = warp-per-node dot product s[n]=x[n]·w;
// blocks [NB_NODE, NB_NODE+NB_EDGE) = degree atomics over edges.
// The 20 MB x-stream hides the degree-atomic drain.
// ---------------------------------------------------------------------------
__global__ void dot_and_deg_kernel(const float* __restrict__ x,
                                   const int* __restrict__ ebuf) {
    int blk = blockIdx.x;
    int t = threadIdx.x;

    if (blk < NB_NODE) {
        __shared__ float sw[F_IN];
        for (int i = t; i < F_IN; i += blockDim.x) sw[i] = g_w[i];
        __syncthreads();

        int node = (blk * 256 + t) >> 5;
        int lane = t & 31;
        if (node >= N_NODES) return;

        const float* xr = x + (long long)node * F_IN;
        float acc = xr[lane]      * sw[lane]
                  + xr[lane + 32] * sw[lane + 32]
                  + xr[lane + 64] * sw[lane + 64];
        if (lane < 4) acc += xr[lane + 96] * sw[lane + 96];

        #pragma unroll
        for (int o = 16; o > 0; o >>= 1)
            acc += __shfl_down_sync(0xffffffffu, acc, o);

        if (lane == 0) g_s[node] = acc;
        return;
    }
    // degree accumulation
    int e = (blk - NB_NODE) * 256 + t;
    if (e < N_EDGES) {
        int dst = load_edge(ebuf, (long long)N_EDGES + e);
        if (dst >= 0 && dst < N_NODES)
            atomicAdd(&g_deg[dst], 1.0f);
    }
}

// ---------------------------------------------------------------------------
// K3: per-node finalize: dinv, p, and out = self-loop + folded bias
// ---------------------------------------------------------------------------
__global__ void node_finalize(float* __restrict__ out) {
    int n = blockIdx.x * blockDim.x + threadIdx.x;
    if (n < N_NODES) {
        float d = rsqrtf(g_deg[n]);       // deg >= 1 always (self loop)
        float s = g_s[n];
        g_dinv[n] = d;
        g_p[n]    = s * d;
        out[n]    = g_c + s * d * d;
    }
}

// ---------------------------------------------------------------------------
// K4: edge scatter: out[dst] += p[src] * dinv[dst]
// ---------------------------------------------------------------------------
__global__ void edge_scatter(const int* __restrict__ ebuf,
                             float* __restrict__ out) {
    int e = blockIdx.x * blockDim.x + threadIdx.x;
    if (e < N_EDGES) {
        int s = load_edge(ebuf, e);
        int d = load_edge(ebuf, (long long)N_EDGES + e);
        if (s >= 0 && s < N_NODES && d >= 0 && d < N_NODES)
            atomicAdd(&out[d], g_p[s] * g_dinv[d]);
    }
}

extern "C" void kernel_launch(void* const* d_in, const int* in_sizes, int n_in,
                              void* d_out, int out_size) {
    const float* state = (const float*)d_in[0];  // [N, 100, 1] f32
    const int*   ebuf  = (const int*)  d_in[1];  // [2, 200000] int32 or int64 layout
    const float* W1    = (const float*)d_in[2];  // [100, 1024]
    const float* b1    = (const float*)d_in[3];  // [1024]
    const float* Wh    = (const float*)d_in[4];  // [1024, 1]
    const float* bh    = (const float*)d_in[5];  // [1]
    float* out = (float*)d_out;                  // [N, 1]

    setup_kernel     <<<1 + (F_IN + 1) + NB_DEG, 256>>>(ebuf, W1, b1, Wh, bh);
    dot_and_deg_kernel<<<NB_NODE + NB_EDGE, 256>>>(state, ebuf);
    node_finalize    <<<NB_DEG, 256>>>(out);
    edge_scatter     <<<NB_EDGE, 256>>>(ebuf, out);
}